// round 15
// baseline (speedup 1.0000x reference)
#include <cuda_runtime.h>
#include <cuda_fp16.h>
#include <math.h>

#define N_INST 16384
#define NB1    1024
#define NB2    64
#define DIM    1024
#define NATT   256
#define NCLS   512

// ---------------- scratch (device globals; no allocation allowed) ----------
__device__ float g_emb1[N_INST * DIM];   // 64 MB (fp32 for segsum accuracy)
__device__ float g_emb2[NB1 * DIM];
__device__ float g_emb3[NB2 * DIM];
__device__ float g_s[N_INST + NB1 + NB2];
__device__ float g_stats[8];
// conv2 weights, transposed [n=64][k=800], fp16
__device__ __half g_w2t[64 * 800];
// embeddings as fp16 (A-side of attention GEMMs)
__device__ __half g_emb1f16[N_INST * DIM];
__device__ __half g_emb2f16[NB1 * DIM];
__device__ __half g_emb3f16[NB2 * DIM];
// attention weights, transposed [n=256][k=1024], fp16, 3 levels
__device__ __half g_awt[3 * NATT * DIM];

__device__ __forceinline__ float* emb_buf(int lvl) {
    return lvl == 0 ? g_emb1 : (lvl == 1 ? g_emb2 : g_emb3);
}
__device__ __forceinline__ float* s_buf(int lvl) {
    return lvl == 0 ? g_s : (lvl == 1 ? g_s + N_INST : g_s + N_INST + NB1);
}

// ---------------- mma helpers ----------------------------------------------
__device__ __forceinline__ void ldsm4(unsigned& r0, unsigned& r1, unsigned& r2,
                                      unsigned& r3, unsigned a) {
    asm volatile("ldmatrix.sync.aligned.m8n8.x4.shared.b16 {%0,%1,%2,%3}, [%4];"
                 : "=r"(r0), "=r"(r1), "=r"(r2), "=r"(r3) : "r"(a));
}
__device__ __forceinline__ void mma_f16(float* c, unsigned a0, unsigned a1,
                                        unsigned a2, unsigned a3,
                                        unsigned b0, unsigned b1) {
    asm volatile(
        "mma.sync.aligned.m16n8k16.row.col.f32.f16.f16.f32 "
        "{%0,%1,%2,%3},{%4,%5,%6,%7},{%8,%9},{%0,%1,%2,%3};"
        : "+f"(c[0]), "+f"(c[1]), "+f"(c[2]), "+f"(c[3])
        : "r"(a0), "r"(a1), "r"(a2), "r"(a3), "r"(b0), "r"(b1));
}

// ---------------------------------------------------------------------------
// Prep kernels: weight transposes to fp16
// ---------------------------------------------------------------------------
__global__ __launch_bounds__(256) void prep_w2t(const float* __restrict__ w2) {
    const int idx = blockIdx.x * 256 + threadIdx.x;
    if (idx >= 64 * 800) return;
    const int n = idx / 800, k = idx - n * 800;
    g_w2t[idx] = __float2half(w2[k * 64 + n]);
}

__global__ __launch_bounds__(256) void prep_awt_all(
    const float* __restrict__ W0, const float* __restrict__ W1,
    const float* __restrict__ W2)
{
    const int gidx = blockIdx.x * 256 + threadIdx.x;   // 3*262144
    const int set = gidx >> 18;
    const int idx = gidx & 262143;
    const float* W = set == 0 ? W0 : (set == 1 ? W1 : W2);
    const int n = idx >> 10, k = idx & 1023;
    g_awt[set * (NATT * DIM) + idx] = __float2half(W[k * NATT + n]);
}

// ---------------------------------------------------------------------------
// Fused conv kernel: one CTA = 2 images; 2 CTAs/SM.
// Phase A: conv1 on tensor cores (R14, unchanged math).
// Phase B: conv2 implicit GEMM, single-term fp16 mma, DOUBLE-BUFFERED slabs.
// smem map (bytes):
//   0     p1[2 img][144*40 fp16]                          23040
//   23040 shared region: PhaseA Abuf (30720)
//                        PhaseB slab buf0/buf1 (2x21504)  43008
//   66048 in16[2 img][784 fp16]                            3136
//   69184 w1B [32 n][40 fp16] (taps>=25 zero)              2560
//   71744 b1_s[32 f]                                        128
// ---------------------------------------------------------------------------
#define FC_SMEM 71872

__global__ __launch_bounds__(256, 2) void fused_conv_kernel(
    const float* __restrict__ x,
    const float* __restrict__ w1, const float* __restrict__ b1,
    const float* __restrict__ b2)
{
    extern __shared__ char smem[];
    const unsigned sbase = (unsigned)__cvta_generic_to_shared(smem);
    const int tid = threadIdx.x;
    const int l = tid & 31, w = tid >> 5;
    const int lane_r = ((l >> 3) & 1) * 8 + (l & 7);
    const unsigned khalf = ((l >> 4) & 1) * 16;

    __half* p1   = (__half*)smem;              // [img][144*40]
    __half* Abuf = (__half*)(smem + 23040);    // [img][192*40]
    __half* in16 = (__half*)(smem + 66048);    // [img][784]
    __half* w1B  = (__half*)(smem + 69184);    // [32][40]
    float*  b1_s = (float*)(smem + 71744);

    // ---------------- Phase A: conv1 via tensor cores ---------------------
    {
        const float* x0 = x + (size_t)blockIdx.x * 2 * 784;
        for (int i = tid; i < 1568; i += 256) in16[i] = __float2half(x0[i]);
        for (int i = tid; i < 1280; i += 256) {          // 32 rows x 40 cols
            const int n = i / 40, c = i - n * 40;
            const float v = (c < 25) ? w1[c * 32 + n] : 0.f;
            w1B[n * 40 + c] = __float2half(v);
        }
        if (tid < 32) b1_s[tid] = b1[tid];
        {
            const uint4 z4 = make_uint4(0u, 0u, 0u, 0u);
            for (int i = tid; i < 1920; i += 256)
                *(uint4*)(smem + 23040 + i * 16) = z4;
        }
        __syncthreads();

        // per-warp B fragments (same w1 for both images), held in registers
        unsigned wb[16];
        {
            const unsigned bB = sbase + 69184 + (unsigned)l * 80;
            ldsm4(wb[0],  wb[1],  wb[2],  wb[3],  bB);
            ldsm4(wb[4],  wb[5],  wb[6],  wb[7],  bB + 16);
            ldsm4(wb[8],  wb[9],  wb[10], wb[11], bB + 32);
            ldsm4(wb[12], wb[13], wb[14], wb[15], bB + 48);
        }

        const int wimg = w >> 2;     // image this warp computes
        const int wq   = w & 3;      // tile group within chunk

        for (int chunk = 0; chunk < 3; chunk++) {
            // ---- build A chunk: 192 rows x 25 taps, both images ----
            for (int slot = tid; slot < 384; slot += 256) {
                const int bimg = slot >= 192;
                const int rl   = slot - bimg * 192;
                const int p    = chunk * 48 + (rl >> 2);
                const int mem  = rl & 3;
                const int pr = p / 12, pc = p - pr * 12;
                const __half* src =
                    in16 + bimg * 784 +
                    (2 * pr + (mem >> 1)) * 28 + 2 * pc + (mem & 1);
                __half* dst = Abuf + bimg * 7680 + rl * 40;
                #pragma unroll
                for (int ky = 0; ky < 5; ky++)
                    #pragma unroll
                    for (int kx = 0; kx < 5; kx++)
                        dst[ky * 5 + kx] = src[ky * 28 + kx];
            }
            __syncthreads();

            // ---- mma + pooled epilogue: 12 m-tiles, 3 per warp ----
            const unsigned AbB = sbase + 23040 + (unsigned)wimg * 15360;
            #pragma unroll
            for (int ti = 0; ti < 3; ti++) {
                const int tile = wq + ti * 4;
                const unsigned ar = AbB + (unsigned)(tile * 16 + lane_r) * 80;
                unsigned a0, a1, a2, a3, a4, a5, a6, a7;
                ldsm4(a0, a1, a2, a3, ar + khalf);        // k0-15
                ldsm4(a4, a5, a6, a7, ar + 32 + khalf);   // k16-31

                float acc[4][4];
                #pragma unroll
                for (int j = 0; j < 4; j++)
                    #pragma unroll
                    for (int q = 0; q < 4; q++) acc[j][q] = 0.f;
                #pragma unroll
                for (int j = 0; j < 4; j++) {
                    mma_f16(acc[j], a0, a1, a2, a3, wb[j], wb[4 + j]);
                    mma_f16(acc[j], a4, a5, a6, a7, wb[8 + j], wb[12 + j]);
                }

                // pool over the 4 member-rows inside the fragment
                const int pbase = chunk * 48 + tile * 4;
                #pragma unroll
                for (int j = 0; j < 4; j++) {
                    float m0 = acc[j][0], m1 = acc[j][1];
                    float m2 = acc[j][2], m3 = acc[j][3];
                    m0 = fmaxf(m0, __shfl_xor_sync(0xffffffffu, m0, 4));
                    m0 = fmaxf(m0, __shfl_xor_sync(0xffffffffu, m0, 8));
                    m1 = fmaxf(m1, __shfl_xor_sync(0xffffffffu, m1, 4));
                    m1 = fmaxf(m1, __shfl_xor_sync(0xffffffffu, m1, 8));
                    m2 = fmaxf(m2, __shfl_xor_sync(0xffffffffu, m2, 4));
                    m2 = fmaxf(m2, __shfl_xor_sync(0xffffffffu, m2, 8));
                    m3 = fmaxf(m3, __shfl_xor_sync(0xffffffffu, m3, 4));
                    m3 = fmaxf(m3, __shfl_xor_sync(0xffffffffu, m3, 8));
                    if ((l & 12) == 0) {
                        const int q  = l >> 4;               // 0/1
                        const int ch = j * 8 + 2 * (l & 3);
                        const float bA = b1_s[ch], bB2 = b1_s[ch + 1];
                        __half2 o1, o2;
                        o1.x = __float2half(fmaxf(m0 + bA, 0.f));
                        o1.y = __float2half(fmaxf(m1 + bB2, 0.f));
                        o2.x = __float2half(fmaxf(m2 + bA, 0.f));
                        o2.y = __float2half(fmaxf(m3 + bB2, 0.f));
                        __half* pp = p1 + wimg * 5760;
                        *(__half2*)&pp[(pbase + q) * 40 + ch]     = o1;
                        *(__half2*)&pp[(pbase + 2 + q) * 40 + ch] = o2;
                    }
                }
            }
            __syncthreads();   // mma done before next build / Phase B staging
        }
    }

    // ---------------- Phase B: conv2 via fp16 tensor-core GEMM ------------
    // 8 warps = 2 img x 2 m-pairs x 2 n-halves; each warp m32 x n32.
    // Double-buffered weight slabs: stage ky+1 while computing ky.
    {
        const int img = w >> 2;
        const int mp  = (w >> 1) & 1;
        const int nh  = w & 1;

        unsigned abase[2];
        #pragma unroll
        for (int s = 0; s < 2; s++) {
            const int pos = (mp * 2 + s) * 16 + lane_r;
            abase[s] = (unsigned)(((pos >> 3) * 12 + (pos & 7)) * 80);
        }

        const unsigned aHb = sbase + img * 11520;

        float acc[2][4][4];
        #pragma unroll
        for (int s = 0; s < 2; s++)
            #pragma unroll
            for (int j = 0; j < 4; j++)
                #pragma unroll
                for (int q = 0; q < 4; q++) acc[s][j][q] = 0.f;

        const char* wt = (const char*)g_w2t;

        // stage slab 0 (Abuf dead after Phase A's final barrier)
        for (int i = tid; i < 1280; i += 256) {
            const int n = i / 20, c = i - n * 20;
            *(uint4*)(smem + 23040 + n * 336 + c * 16) =
                *(const uint4*)(wt + n * 1600 + c * 16);
        }
        __syncthreads();

        for (int ky = 0; ky < 5; ky++) {
            // prefetch slab ky+1 into the other buffer (writes the buffer
            // nobody reads this iteration; end-of-iter barrier covers it)
            if (ky < 4) {
                const int buf = (ky + 1) & 1;
                for (int i = tid; i < 1280; i += 256) {
                    const int n = i / 20, c = i - n * 20;
                    *(uint4*)(smem + 23040 + buf * 21504 + n * 336 + c * 16) =
                        *(const uint4*)(wt + n * 1600 + (ky + 1) * 320 + c * 16);
                }
            }

            const unsigned BHb = sbase + 23040 + (unsigned)(ky & 1) * 21504;
            const unsigned kyoff = (unsigned)ky * 960;
            for (int kx = 0; kx < 5; kx++) {
                #pragma unroll
                for (int hf = 0; hf < 2; hf++) {
                    const unsigned kb = (unsigned)(kx * 2 + hf) * 32;
                    const unsigned brow = (unsigned)(nh * 32 + l) * 336 + kb;
                    unsigned bh[8];
                    ldsm4(bh[0], bh[1], bh[2], bh[3], BHb + brow);
                    ldsm4(bh[4], bh[5], bh[6], bh[7], BHb + brow + 16);

                    #pragma unroll
                    for (int s = 0; s < 2; s++) {
                        const unsigned ab =
                            abase[s] + kyoff + kx * 80 + khalf + hf * 32;
                        unsigned ah0, ah1, ah2, ah3;
                        ldsm4(ah0, ah1, ah2, ah3, aHb + ab);
                        #pragma unroll
                        for (int j = 0; j < 4; j++)
                            mma_f16(acc[s][j], ah0, ah1, ah2, ah3, bh[j], bh[4 + j]);
                    }
                }
            }
            __syncthreads();   // compute of ky done; staging of ky+1 done
        }

        // epilogue: 2x2 maxpool + bias + relu -> emb1 (fp32 + fp16)
        const long row_img = (long)blockIdx.x * 2 + img;
        #pragma unroll
        for (int s = 0; s < 2; s++) {
            const int mt = mp * 2 + s;
            #pragma unroll
            for (int j = 0; j < 4; j++) {
                float v0 = fmaxf(acc[s][j][0], acc[s][j][2]);
                float v1 = fmaxf(acc[s][j][1], acc[s][j][3]);
                const float u0 = fmaxf(v0, __shfl_down_sync(0xffffffffu, v0, 4));
                const float u1 = fmaxf(v1, __shfl_down_sync(0xffffffffu, v1, 4));
                if (((l >> 2) & 1) == 0) {
                    const int pc = l >> 3;
                    const int p  = mt * 4 + pc;
                    const int nn = nh * 32 + j * 8 + 2 * (l & 3);
                    float2 o;
                    o.x = fmaxf(u0 + b2[nn], 0.f);
                    o.y = fmaxf(u1 + b2[nn + 1], 0.f);
                    const long base = row_img * DIM + p * 64 + nn;
                    *(float2*)&g_emb1[base] = o;
                    __half2 hh;
                    hh.x = __float2half(o.x);
                    hh.y = __float2half(o.y);
                    *(__half2*)&g_emb1f16[base] = hh;
                }
            }
        }
    }
}

// ---------------------------------------------------------------------------
// Tensor-core attention: CTA = 64 rows x 256 units; warps m32 x n64.
// A = emb fp16; B = weights fp16; single-term mma.
// DOUBLE-BUFFERED staging: buf k = (kc&1)*46080; each buf: A@+0, B@+9216.
// smem: buf0@0 buf1@46080 sb@92160 sv@93184 wred@94208 -> 95232
// ---------------------------------------------------------------------------
#define ATT_SMEM 95232

__global__ __launch_bounds__(256, 2) void att_mma_kernel(
    int lvl, const float* __restrict__ b, const float* __restrict__ v,
    const float* __restrict__ vb)
{
    extern __shared__ char sm[];
    const unsigned sb32 = (unsigned)__cvta_generic_to_shared(sm);
    const int tid = threadIdx.x;
    const int row0 = blockIdx.x * 64;

    const __half* ef = lvl == 0 ? g_emb1f16 : (lvl == 1 ? g_emb2f16 : g_emb3f16);
    const __half* wh = g_awt + (size_t)lvl * (NATT * DIM);
    float* s_out = s_buf(lvl);

    float* sbf  = (float*)(sm + 92160);
    float* svf  = (float*)(sm + 93184);
    float* wred = (float*)(sm + 94208);   // [64 rows][4 quarters]
    sbf[tid] = b[tid];
    svf[tid] = v[tid];

    const int l  = tid & 31, w = tid >> 5;
    const int mp = w >> 2;     // m half (rows 0-31 / 32-63)
    const int nq = w & 3;      // n quarter (64 cols)
    const int lane_r = ((l >> 3) & 1) * 8 + (l & 7);
    const unsigned khalf = ((l >> 4) & 1) * 16;

    float acc[2][8][4];
    #pragma unroll
    for (int s = 0; s < 2; s++)
        #pragma unroll
        for (int j = 0; j < 8; j++)
            #pragma unroll
            for (int q = 0; q < 4; q++) acc[s][j][q] = 0.f;

    // stage k-chunk kc into buffer ofs
    auto stage = [&](int kc, int ofs) {
        const int k0 = kc * 64;
        for (int i = tid; i < 512; i += 256) {           // A: 64 rows x 64 k
            const int r = i >> 3, c = i & 7;
            const __half* src = ef + (size_t)(row0 + r) * DIM + k0 + c * 8;
            *(uint4*)(sm + ofs + r * 144 + c * 16) = *(const uint4*)src;
        }
        for (int i = tid; i < 2048; i += 256) {          // B: 256 n x 64 k
            const int n = i >> 3, c = i & 7;
            const __half* src = wh + (size_t)n * DIM + k0 + c * 8;
            *(uint4*)(sm + ofs + 9216 + n * 144 + c * 16) = *(const uint4*)src;
        }
    };

    stage(0, 0);
    __syncthreads();

    for (int kc = 0; kc < 16; kc++) {
        if (kc < 15) stage(kc + 1, ((kc + 1) & 1) * 46080);

        const unsigned bo = sb32 + (unsigned)((kc & 1) * 46080);
        #pragma unroll
        for (int ks = 0; ks < 4; ks++) {
            unsigned ah[2][4];
            #pragma unroll
            for (int s = 0; s < 2; s++) {
                const unsigned aoff =
                    (unsigned)(mp * 32 + s * 16 + lane_r) * 144 + ks * 32 + khalf;
                ldsm4(ah[s][0], ah[s][1], ah[s][2], ah[s][3], bo + aoff);
            }
            #pragma unroll
            for (int g = 0; g < 2; g++) {
                const unsigned boff =
                    (unsigned)(nq * 64 + g * 32 + l) * 144 + ks * 32;
                unsigned b0h[4], b1h[4];
                ldsm4(b0h[0], b0h[1], b0h[2], b0h[3], bo + 9216 + boff);
                ldsm4(b1h[0], b1h[1], b1h[2], b1h[3], bo + 9216 + boff + 16);
                #pragma unroll
                for (int s = 0; s < 2; s++) {
                    #pragma unroll
                    for (int jj = 0; jj < 4; jj++)
                        mma_f16(acc[s][g * 4 + jj],
                                ah[s][0], ah[s][1], ah[s][2], ah[s][3],
                                b0h[jj], b1h[jj]);
                }
            }
        }
        __syncthreads();   // compute of kc done; staging of kc+1 done
    }

    // epilogue: tanh(h+b)*v, reduce over n -> per-row partials
    #pragma unroll
    for (int s = 0; s < 2; s++) {
        float pvA = 0.f, pvB = 0.f;
        #pragma unroll
        for (int j = 0; j < 8; j++) {
            const int n = nq * 64 + j * 8 + (l & 3) * 2;
            const float b0v = sbf[n], b1v = sbf[n + 1];
            const float v0 = svf[n], v1 = svf[n + 1];
            pvA += tanhf(acc[s][j][0] + b0v) * v0 + tanhf(acc[s][j][1] + b1v) * v1;
            pvB += tanhf(acc[s][j][2] + b0v) * v0 + tanhf(acc[s][j][3] + b1v) * v1;
        }
        pvA += __shfl_xor_sync(0xffffffffu, pvA, 1);
        pvA += __shfl_xor_sync(0xffffffffu, pvA, 2);
        pvB += __shfl_xor_sync(0xffffffffu, pvB, 1);
        pvB += __shfl_xor_sync(0xffffffffu, pvB, 2);
        if ((l & 3) == 0) {
            const int r = mp * 32 + s * 16 + (l >> 2);
            wred[r * 4 + nq]       = pvA;
            wred[(r + 8) * 4 + nq] = pvB;
        }
    }
    __syncthreads();
    if (tid < 64) {
        const float z = wred[tid * 4] + wred[tid * 4 + 1] +
                        wred[tid * 4 + 2] + wred[tid * 4 + 3] + vb[0];
        s_out[row0 + tid] = 1.f / (1.f + expf(-z));
    }
}

// ---------------------------------------------------------------------------
__global__ __launch_bounds__(1024) void stats_kernel(int lvl, int R)
{
    __shared__ float red[1024];
    const float* s = s_buf(lvl);
    const int tid = threadIdx.x;

    float m = -1e30f;
    for (int i = tid; i < R; i += 1024) m = fmaxf(m, s[i]);
    red[tid] = m; __syncthreads();
    for (int off = 512; off; off >>= 1) {
        if (tid < off) red[tid] = fmaxf(red[tid], red[tid + off]);
        __syncthreads();
    }
    const float mx = red[0];
    __syncthreads();

    float sum = 0.f;
    for (int i = tid; i < R; i += 1024) sum += expf(s[i] - mx);
    red[tid] = sum; __syncthreads();
    for (int off = 512; off; off >>= 1) {
        if (tid < off) red[tid] += red[tid + off];
        __syncthreads();
    }
    if (tid == 0) { g_stats[lvl * 2] = mx; g_stats[lvl * 2 + 1] = red[0]; }
}

// ---------------------------------------------------------------------------
// segsum: weighted bag pooling (fp32) + emit fp16 emb for next attention
// ---------------------------------------------------------------------------
__global__ __launch_bounds__(256) void segsum_kernel(int lvl)
{
    __shared__ float ws[16];
    const float* ein  = emb_buf(lvl);
    float*       eout = emb_buf(lvl + 1);
    __half* eoutf = lvl == 0 ? g_emb2f16 : g_emb3f16;
    const float* s    = s_buf(lvl);
    const int bg = blockIdx.x, tid = threadIdx.x;

    if (tid < 16) {
        const float mx = g_stats[lvl * 2];
        const float inv = 1.f / g_stats[lvl * 2 + 1];
        ws[tid] = expf(s[bg * 16 + tid] - mx) * inv;
    }
    __syncthreads();

    const float4* base = (const float4*)(ein + (long)bg * 16 * DIM);
    float4* dst = (float4*)(eout + (long)bg * DIM);
    for (int d = tid; d < DIM / 4; d += 256) {
        float4 a = make_float4(0.f, 0.f, 0.f, 0.f);
        #pragma unroll
        for (int i = 0; i < 16; i++) {
            const float w = ws[i];
            const float4 e = base[i * (DIM / 4) + d];
            a.x += w * e.x; a.y += w * e.y; a.z += w * e.z; a.w += w * e.w;
        }
        dst[d] = a;
        const long eb = (long)bg * DIM + d * 4;
        eoutf[eb + 0] = __float2half(a.x);
        eoutf[eb + 1] = __float2half(a.y);
        eoutf[eb + 2] = __float2half(a.z);
        eoutf[eb + 3] = __float2half(a.w);
    }
}

// ---------------------------------------------------------------------------
__global__ __launch_bounds__(512) void final_kernel(
    const float* __restrict__ clsW, const float* __restrict__ clsb,
    const float* __restrict__ outW, const float* __restrict__ outb,
    float* __restrict__ out)
{
    __shared__ float w3[64];
    __shared__ float outer[DIM];
    __shared__ float red[512];
    const int tid = threadIdx.x;
    const float* s3 = s_buf(2);

    if (tid == 0) {
        float mx = -1e30f;
        for (int i = 0; i < 64; i++) mx = fmaxf(mx, s3[i]);
        float sum = 0.f;
        for (int i = 0; i < 64; i++) { float e = expf(s3[i] - mx); w3[i] = e; sum += e; }
        const float inv = 1.f / sum;
        for (int i = 0; i < 64; i++) w3[i] *= inv;
    }
    __syncthreads();

    for (int d = tid; d < DIM; d += 512) {
        float acc = 0.f;
        #pragma unroll 8
        for (int b2 = 0; b2 < 64; b2++) acc += w3[b2] * g_emb3[b2 * DIM + d];
        outer[d] = acc;
    }
    __syncthreads();

    float acc = 0.f;
    const float* wp = clsW + tid;
    for (int d = 0; d < DIM; d++) acc += outer[d] * wp[d * NCLS];
    red[tid] = (acc + clsb[tid]) * outW[tid];
    __syncthreads();
    for (int off = 256; off; off >>= 1) {
        if (tid < off) red[tid] += red[tid + off];
        __syncthreads();
    }
    if (tid == 0) out[0] = 1.f / (1.f + expf(-(red[0] + outb[0])));
}

// ---------------------------------------------------------------------------
extern "C" void kernel_launch(void* const* d_in, const int* in_sizes, int n_in,
                              void* d_out, int out_size)
{
    const float* x    = (const float*)d_in[0];
    const float* c1w  = (const float*)d_in[1];
    const float* c1b  = (const float*)d_in[2];
    const float* c2w  = (const float*)d_in[3];
    const float* c2b  = (const float*)d_in[4];
    const float* a1W  = (const float*)d_in[5];
    const float* a1b  = (const float*)d_in[6];
    const float* a1v  = (const float*)d_in[7];
    const float* a1vb = (const float*)d_in[8];
    const float* a2W  = (const float*)d_in[9];
    const float* a2b  = (const float*)d_in[10];
    const float* a2v  = (const float*)d_in[11];
    const float* a2vb = (const float*)d_in[12];
    const float* a3W  = (const float*)d_in[13];
    const float* a3b  = (const float*)d_in[14];
    const float* a3v  = (const float*)d_in[15];
    const float* a3vb = (const float*)d_in[16];
    const float* clsW = (const float*)d_in[17];
    const float* clsb = (const float*)d_in[18];
    const float* outW = (const float*)d_in[19];
    const float* outb = (const float*)d_in[20];

    cudaFuncSetAttribute(fused_conv_kernel,
                         cudaFuncAttributeMaxDynamicSharedMemorySize, FC_SMEM);
    cudaFuncSetAttribute(att_mma_kernel,
                         cudaFuncAttributeMaxDynamicSharedMemorySize, ATT_SMEM);

    prep_w2t<<<200, 256>>>(c2w);
    prep_awt_all<<<3072, 256>>>(a1W, a2W, a3W);

    fused_conv_kernel<<<N_INST / 2, 256, FC_SMEM>>>(x, c1w, c1b, c2b);

    att_mma_kernel<<<N_INST / 64, 256, ATT_SMEM>>>(0, a1b, a1v, a1vb);
    stats_kernel<<<1, 1024>>>(0, N_INST);
    segsum_kernel<<<NB1, 256>>>(0);

    att_mma_kernel<<<NB1 / 64, 256, ATT_SMEM>>>(1, a2b, a2v, a2vb);
    stats_kernel<<<1, 1024>>>(1, NB1);
    segsum_kernel<<<NB2, 256>>>(1);

    att_mma_kernel<<<NB2 / 64, 256, ATT_SMEM>>>(2, a3b, a3v, a3vb);
    final_kernel<<<1, 512>>>(clsW, clsb, outW, outb, (float*)d_out);
}

// round 16
// speedup vs baseline: 1.0547x; 1.0547x over previous
#include <cuda_runtime.h>
#include <cuda_fp16.h>
#include <math.h>

#define N_INST 16384
#define NB1    1024
#define NB2    64
#define DIM    1024
#define NATT   256
#define NCLS   512

// ---------------- scratch (device globals; no allocation allowed) ----------
__device__ float g_emb2[NB1 * DIM];      // fp32 bag embeddings (small)
__device__ float g_emb3[NB2 * DIM];
__device__ float g_s[N_INST + NB1 + NB2];
__device__ float g_part[3][256];         // per-CTA partial sums of exp(s-1)
// conv2 weights, transposed [n=64][k=800], fp16
__device__ __half g_w2t[64 * 800];
// embeddings as fp16 (A-side of attention GEMMs; emb1 exists ONLY as fp16)
__device__ __half g_emb1f16[N_INST * DIM];
__device__ __half g_emb2f16[NB1 * DIM];
__device__ __half g_emb3f16[NB2 * DIM];
// attention weights, transposed [n=256][k=1024], fp16, 3 levels
__device__ __half g_awt[3 * NATT * DIM];

__device__ __forceinline__ float* s_buf(int lvl) {
    return lvl == 0 ? g_s : (lvl == 1 ? g_s + N_INST : g_s + N_INST + NB1);
}

// ---------------- mma helpers ----------------------------------------------
__device__ __forceinline__ void ldsm4(unsigned& r0, unsigned& r1, unsigned& r2,
                                      unsigned& r3, unsigned a) {
    asm volatile("ldmatrix.sync.aligned.m8n8.x4.shared.b16 {%0,%1,%2,%3}, [%4];"
                 : "=r"(r0), "=r"(r1), "=r"(r2), "=r"(r3) : "r"(a));
}
__device__ __forceinline__ void mma_f16(float* c, unsigned a0, unsigned a1,
                                        unsigned a2, unsigned a3,
                                        unsigned b0, unsigned b1) {
    asm volatile(
        "mma.sync.aligned.m16n8k16.row.col.f32.f16.f16.f32 "
        "{%0,%1,%2,%3},{%4,%5,%6,%7},{%8,%9},{%0,%1,%2,%3};"
        : "+f"(c[0]), "+f"(c[1]), "+f"(c[2]), "+f"(c[3])
        : "r"(a0), "r"(a1), "r"(a2), "r"(a3), "r"(b0), "r"(b1));
}

// ---------------------------------------------------------------------------
// Prep: all weight transposes to fp16 in ONE launch.
//   idx < 786432 : attention weights (3 sets of [n=256][k=1024])
//   else         : conv2 weights ([n=64][k=800])
// ---------------------------------------------------------------------------
__global__ __launch_bounds__(256) void prep_all(
    const float* __restrict__ W0, const float* __restrict__ W1,
    const float* __restrict__ W2, const float* __restrict__ w2)
{
    const int gidx = blockIdx.x * 256 + threadIdx.x;
    if (gidx < 786432) {
        const int set = gidx >> 18;
        const int idx = gidx & 262143;
        const float* W = set == 0 ? W0 : (set == 1 ? W1 : W2);
        const int n = idx >> 10, k = idx & 1023;
        g_awt[set * (NATT * DIM) + idx] = __float2half(W[k * NATT + n]);
    } else {
        const int idx = gidx - 786432;
        if (idx < 64 * 800) {
            const int n = idx / 800, k = idx - n * 800;
            g_w2t[idx] = __float2half(w2[k * 64 + n]);
        }
    }
}

// ---------------------------------------------------------------------------
// Fused conv kernel (R14 structure): one CTA = 2 images; 2 CTAs/SM.
// Phase A: conv1 on tensor cores (chunked row-copy im2col).
// Phase B: conv2 implicit GEMM, single-term fp16 mma, single-buffer slabs.
// Epilogue writes emb1 ONLY as fp16.
// smem map (bytes):
//   0     p1[2 img][144*40 fp16]                 23040
//   23040 Abuf (30720) / PhaseB slab (21504)
//   53760 in16[2 img][784 fp16]                   3136
//   56896 w1B [32 n][40 fp16] (taps>=25 zero)     2560
//   59456 b1_s[32 f]                               128
// ---------------------------------------------------------------------------
#define FC_SMEM 59584

__global__ __launch_bounds__(256, 2) void fused_conv_kernel(
    const float* __restrict__ x,
    const float* __restrict__ w1, const float* __restrict__ b1,
    const float* __restrict__ b2)
{
    extern __shared__ char smem[];
    const unsigned sbase = (unsigned)__cvta_generic_to_shared(smem);
    const int tid = threadIdx.x;
    const int l = tid & 31, w = tid >> 5;
    const int lane_r = ((l >> 3) & 1) * 8 + (l & 7);
    const unsigned khalf = ((l >> 4) & 1) * 16;

    __half* p1   = (__half*)smem;              // [img][144*40]
    __half* Abuf = (__half*)(smem + 23040);    // [img][192*40]
    __half* in16 = (__half*)(smem + 53760);    // [img][784]
    __half* w1B  = (__half*)(smem + 56896);    // [32][40]
    float*  b1_s = (float*)(smem + 59456);

    // ---------------- Phase A: conv1 via tensor cores ---------------------
    {
        const float* x0 = x + (size_t)blockIdx.x * 2 * 784;
        for (int i = tid; i < 1568; i += 256) in16[i] = __float2half(x0[i]);
        for (int i = tid; i < 1280; i += 256) {          // 32 rows x 40 cols
            const int n = i / 40, c = i - n * 40;
            const float v = (c < 25) ? w1[c * 32 + n] : 0.f;
            w1B[n * 40 + c] = __float2half(v);
        }
        if (tid < 32) b1_s[tid] = b1[tid];
        {
            const uint4 z4 = make_uint4(0u, 0u, 0u, 0u);
            for (int i = tid; i < 1920; i += 256)
                *(uint4*)(smem + 23040 + i * 16) = z4;
        }
        __syncthreads();

        unsigned wb[16];
        {
            const unsigned bB = sbase + 56896 + (unsigned)l * 80;
            ldsm4(wb[0],  wb[1],  wb[2],  wb[3],  bB);
            ldsm4(wb[4],  wb[5],  wb[6],  wb[7],  bB + 16);
            ldsm4(wb[8],  wb[9],  wb[10], wb[11], bB + 32);
            ldsm4(wb[12], wb[13], wb[14], wb[15], bB + 48);
        }

        const int wimg = w >> 2;
        const int wq   = w & 3;

        for (int chunk = 0; chunk < 3; chunk++) {
            for (int slot = tid; slot < 384; slot += 256) {
                const int bimg = slot >= 192;
                const int rl   = slot - bimg * 192;
                const int p    = chunk * 48 + (rl >> 2);
                const int mem  = rl & 3;
                const int pr = p / 12, pc = p - pr * 12;
                const __half* src =
                    in16 + bimg * 784 +
                    (2 * pr + (mem >> 1)) * 28 + 2 * pc + (mem & 1);
                __half* dst = Abuf + bimg * 7680 + rl * 40;
                #pragma unroll
                for (int ky = 0; ky < 5; ky++)
                    #pragma unroll
                    for (int kx = 0; kx < 5; kx++)
                        dst[ky * 5 + kx] = src[ky * 28 + kx];
            }
            __syncthreads();

            const unsigned AbB = sbase + 23040 + (unsigned)wimg * 15360;
            #pragma unroll
            for (int ti = 0; ti < 3; ti++) {
                const int tile = wq + ti * 4;
                const unsigned ar = AbB + (unsigned)(tile * 16 + lane_r) * 80;
                unsigned a0, a1, a2, a3, a4, a5, a6, a7;
                ldsm4(a0, a1, a2, a3, ar + khalf);
                ldsm4(a4, a5, a6, a7, ar + 32 + khalf);

                float acc[4][4];
                #pragma unroll
                for (int j = 0; j < 4; j++)
                    #pragma unroll
                    for (int q = 0; q < 4; q++) acc[j][q] = 0.f;
                #pragma unroll
                for (int j = 0; j < 4; j++) {
                    mma_f16(acc[j], a0, a1, a2, a3, wb[j], wb[4 + j]);
                    mma_f16(acc[j], a4, a5, a6, a7, wb[8 + j], wb[12 + j]);
                }

                const int pbase = chunk * 48 + tile * 4;
                #pragma unroll
                for (int j = 0; j < 4; j++) {
                    float m0 = acc[j][0], m1 = acc[j][1];
                    float m2 = acc[j][2], m3 = acc[j][3];
                    m0 = fmaxf(m0, __shfl_xor_sync(0xffffffffu, m0, 4));
                    m0 = fmaxf(m0, __shfl_xor_sync(0xffffffffu, m0, 8));
                    m1 = fmaxf(m1, __shfl_xor_sync(0xffffffffu, m1, 4));
                    m1 = fmaxf(m1, __shfl_xor_sync(0xffffffffu, m1, 8));
                    m2 = fmaxf(m2, __shfl_xor_sync(0xffffffffu, m2, 4));
                    m2 = fmaxf(m2, __shfl_xor_sync(0xffffffffu, m2, 8));
                    m3 = fmaxf(m3, __shfl_xor_sync(0xffffffffu, m3, 4));
                    m3 = fmaxf(m3, __shfl_xor_sync(0xffffffffu, m3, 8));
                    if ((l & 12) == 0) {
                        const int q  = l >> 4;
                        const int ch = j * 8 + 2 * (l & 3);
                        const float bA = b1_s[ch], bB2 = b1_s[ch + 1];
                        __half2 o1, o2;
                        o1.x = __float2half(fmaxf(m0 + bA, 0.f));
                        o1.y = __float2half(fmaxf(m1 + bB2, 0.f));
                        o2.x = __float2half(fmaxf(m2 + bA, 0.f));
                        o2.y = __float2half(fmaxf(m3 + bB2, 0.f));
                        __half* pp = p1 + wimg * 5760;
                        *(__half2*)&pp[(pbase + q) * 40 + ch]     = o1;
                        *(__half2*)&pp[(pbase + 2 + q) * 40 + ch] = o2;
                    }
                }
            }
            __syncthreads();
        }
    }

    // ---------------- Phase B: conv2 via fp16 tensor-core GEMM ------------
    {
        const int img = w >> 2;
        const int mp  = (w >> 1) & 1;
        const int nh  = w & 1;

        unsigned abase[2];
        #pragma unroll
        for (int s = 0; s < 2; s++) {
            const int pos = (mp * 2 + s) * 16 + lane_r;
            abase[s] = (unsigned)(((pos >> 3) * 12 + (pos & 7)) * 80);
        }

        const unsigned aHb = sbase + img * 11520;
        const unsigned BHb = sbase + 23040;

        float acc[2][4][4];
        #pragma unroll
        for (int s = 0; s < 2; s++)
            #pragma unroll
            for (int j = 0; j < 4; j++)
                #pragma unroll
                for (int q = 0; q < 4; q++) acc[s][j][q] = 0.f;

        const char* wt = (const char*)g_w2t;

        for (int ky = 0; ky < 5; ky++) {
            __syncthreads();
            for (int i = tid; i < 1280; i += 256) {
                const int n = i / 20, c = i - n * 20;
                const char* src = wt + n * 1600 + ky * 320 + c * 16;
                char* dst = smem + 23040 + n * 336 + c * 16;
                *(uint4*)dst = *(const uint4*)src;
            }
            __syncthreads();

            const unsigned kyoff = (unsigned)ky * 960;
            for (int kx = 0; kx < 5; kx++) {
                #pragma unroll
                for (int hf = 0; hf < 2; hf++) {
                    const unsigned kb = (unsigned)(kx * 2 + hf) * 32;
                    const unsigned brow = (unsigned)(nh * 32 + l) * 336 + kb;
                    unsigned bh[8];
                    ldsm4(bh[0], bh[1], bh[2], bh[3], BHb + brow);
                    ldsm4(bh[4], bh[5], bh[6], bh[7], BHb + brow + 16);

                    #pragma unroll
                    for (int s = 0; s < 2; s++) {
                        const unsigned ab =
                            abase[s] + kyoff + kx * 80 + khalf + hf * 32;
                        unsigned ah0, ah1, ah2, ah3;
                        ldsm4(ah0, ah1, ah2, ah3, aHb + ab);
                        #pragma unroll
                        for (int j = 0; j < 4; j++)
                            mma_f16(acc[s][j], ah0, ah1, ah2, ah3, bh[j], bh[4 + j]);
                    }
                }
            }
        }

        // epilogue: 2x2 maxpool + bias + relu -> emb1 (fp16 ONLY)
        const long row_img = (long)blockIdx.x * 2 + img;
        #pragma unroll
        for (int s = 0; s < 2; s++) {
            const int mt = mp * 2 + s;
            #pragma unroll
            for (int j = 0; j < 4; j++) {
                float v0 = fmaxf(acc[s][j][0], acc[s][j][2]);
                float v1 = fmaxf(acc[s][j][1], acc[s][j][3]);
                const float u0 = fmaxf(v0, __shfl_down_sync(0xffffffffu, v0, 4));
                const float u1 = fmaxf(v1, __shfl_down_sync(0xffffffffu, v1, 4));
                if (((l >> 2) & 1) == 0) {
                    const int pc = l >> 3;
                    const int p  = mt * 4 + pc;
                    const int nn = nh * 32 + j * 8 + 2 * (l & 3);
                    __half2 hh;
                    hh.x = __float2half(fmaxf(u0 + b2[nn], 0.f));
                    hh.y = __float2half(fmaxf(u1 + b2[nn + 1], 0.f));
                    *(__half2*)&g_emb1f16[row_img * DIM + p * 64 + nn] = hh;
                }
            }
        }
    }
}

// ---------------------------------------------------------------------------
// Tensor-core attention (R14 structure) + per-CTA partial Σexp(s-1) output.
// smem: A@0(9216) B@9216(36864) sb@46080 sv@47104 wred@48128
// ---------------------------------------------------------------------------
#define ATT_SMEM 49152

__global__ __launch_bounds__(256, 2) void att_mma_kernel(
    int lvl, const float* __restrict__ b, const float* __restrict__ v,
    const float* __restrict__ vb)
{
    extern __shared__ char sm[];
    const unsigned sb32 = (unsigned)__cvta_generic_to_shared(sm);
    const int tid = threadIdx.x;
    const int row0 = blockIdx.x * 64;

    const __half* ef = lvl == 0 ? g_emb1f16 : (lvl == 1 ? g_emb2f16 : g_emb3f16);
    const __half* wh = g_awt + (size_t)lvl * (NATT * DIM);
    float* s_out = s_buf(lvl);

    float* sbf  = (float*)(sm + 46080);
    float* svf  = (float*)(sm + 47104);
    float* wred = (float*)(sm + 48128);   // [64 rows][4 quarters]
    sbf[tid] = b[tid];
    svf[tid] = v[tid];

    const int l  = tid & 31, w = tid >> 5;
    const int mp = w >> 2;
    const int nq = w & 3;
    const int lane_r = ((l >> 3) & 1) * 8 + (l & 7);
    const unsigned khalf = ((l >> 4) & 1) * 16;

    float acc[2][8][4];
    #pragma unroll
    for (int s = 0; s < 2; s++)
        #pragma unroll
        for (int j = 0; j < 8; j++)
            #pragma unroll
            for (int q = 0; q < 4; q++) acc[s][j][q] = 0.f;

    for (int kc = 0; kc < 16; kc++) {
        __syncthreads();
        const int k0 = kc * 64;
        for (int i = tid; i < 512; i += 256) {
            const int r = i >> 3, c = i & 7;
            const __half* src = ef + (size_t)(row0 + r) * DIM + k0 + c * 8;
            *(uint4*)(sm + r * 144 + c * 16) = *(const uint4*)src;
        }
        for (int i = tid; i < 2048; i += 256) {
            const int n = i >> 3, c = i & 7;
            const __half* src = wh + (size_t)n * DIM + k0 + c * 8;
            *(uint4*)(sm + 9216 + n * 144 + c * 16) = *(const uint4*)src;
        }
        __syncthreads();

        #pragma unroll
        for (int ks = 0; ks < 4; ks++) {
            unsigned ah[2][4];
            #pragma unroll
            for (int s = 0; s < 2; s++) {
                const unsigned aoff =
                    (unsigned)(mp * 32 + s * 16 + lane_r) * 144 + ks * 32 + khalf;
                ldsm4(ah[s][0], ah[s][1], ah[s][2], ah[s][3], sb32 + aoff);
            }
            #pragma unroll
            for (int g = 0; g < 2; g++) {
                const unsigned boff =
                    (unsigned)(nq * 64 + g * 32 + l) * 144 + ks * 32;
                unsigned b0h[4], b1h[4];
                ldsm4(b0h[0], b0h[1], b0h[2], b0h[3], sb32 + 9216 + boff);
                ldsm4(b1h[0], b1h[1], b1h[2], b1h[3], sb32 + 9216 + boff + 16);
                #pragma unroll
                for (int s = 0; s < 2; s++) {
                    #pragma unroll
                    for (int jj = 0; jj < 4; jj++)
                        mma_f16(acc[s][g * 4 + jj],
                                ah[s][0], ah[s][1], ah[s][2], ah[s][3],
                                b0h[jj], b1h[jj]);
                }
            }
        }
    }

    // epilogue: tanh(h+b)*v, reduce over n -> per-row scores
    #pragma unroll
    for (int s = 0; s < 2; s++) {
        float pvA = 0.f, pvB = 0.f;
        #pragma unroll
        for (int j = 0; j < 8; j++) {
            const int n = nq * 64 + j * 8 + (l & 3) * 2;
            const float b0v = sbf[n], b1v = sbf[n + 1];
            const float v0 = svf[n], v1 = svf[n + 1];
            pvA += tanhf(acc[s][j][0] + b0v) * v0 + tanhf(acc[s][j][1] + b1v) * v1;
            pvB += tanhf(acc[s][j][2] + b0v) * v0 + tanhf(acc[s][j][3] + b1v) * v1;
        }
        pvA += __shfl_xor_sync(0xffffffffu, pvA, 1);
        pvA += __shfl_xor_sync(0xffffffffu, pvA, 2);
        pvB += __shfl_xor_sync(0xffffffffu, pvB, 1);
        pvB += __shfl_xor_sync(0xffffffffu, pvB, 2);
        if ((l & 3) == 0) {
            const int r = mp * 32 + s * 16 + (l >> 2);
            wred[r * 4 + nq]       = pvA;
            wred[(r + 8) * 4 + nq] = pvB;
        }
    }
    __syncthreads();
    if (tid < 64) {
        const float z = wred[tid * 4] + wred[tid * 4 + 1] +
                        wred[tid * 4 + 2] + wred[tid * 4 + 3] + vb[0];
        const float sig = 1.f / (1.f + expf(-z));
        s_out[row0 + tid] = sig;
        sbf[tid] = expf(sig - 1.f);   // sbf no longer needed; reuse
    }
    __syncthreads();
    if (tid < 32) {                   // deterministic partial-sum reduction
        float t = sbf[tid] + sbf[tid + 32];
        #pragma unroll
        for (int off = 16; off; off >>= 1)
            t += __shfl_xor_sync(0xffffffffu, t, off);
        if (tid == 0) g_part[lvl][blockIdx.x] = t;
    }
}

// ---------------------------------------------------------------------------
// segsum: softmax weights from partial sums (shift=1.0) + weighted bag pooling
//   lvl0: reads emb1 fp16, writes emb2 fp32+fp16 (1024 bags)
//   lvl1: reads emb2 fp32, writes emb3 fp32+fp16 (64 bags)
// ---------------------------------------------------------------------------
__global__ __launch_bounds__(256) void segsum_kernel(int lvl)
{
    __shared__ float ws[16];
    __shared__ float sred[8];
    __shared__ float ssum;
    const float* s = s_buf(lvl);
    const int bg = blockIdx.x, tid = threadIdx.x;
    const int lane = tid & 31, wrp = tid >> 5;
    const int nparts = (lvl == 0) ? 256 : 16;

    // deterministic sum of per-CTA partials
    float ps = 0.f;
    for (int i = tid; i < nparts; i += 256) ps += g_part[lvl][i];
    #pragma unroll
    for (int off = 16; off; off >>= 1)
        ps += __shfl_xor_sync(0xffffffffu, ps, off);
    if (lane == 0) sred[wrp] = ps;
    __syncthreads();
    if (tid == 0) {
        float t = 0.f;
        #pragma unroll
        for (int i = 0; i < 8; i++) t += sred[i];
        ssum = t;
    }
    __syncthreads();
    if (tid < 16) ws[tid] = expf(s[bg * 16 + tid] - 1.f) / ssum;
    __syncthreads();

    float*  eout  = (lvl == 0) ? g_emb2 : g_emb3;
    __half* eoutf = (lvl == 0) ? g_emb2f16 : g_emb3f16;

    if (lvl == 0) {
        const __half2* base = (const __half2*)(g_emb1f16 + (long)bg * 16 * DIM);
        for (int d = tid; d < DIM / 2; d += 256) {
            float ax = 0.f, ay = 0.f;
            #pragma unroll
            for (int i = 0; i < 16; i++) {
                const float2 e = __half22float2(base[i * (DIM / 2) + d]);
                ax += ws[i] * e.x; ay += ws[i] * e.y;
            }
            const long eb = (long)bg * DIM + d * 2;
            eout[eb] = ax; eout[eb + 1] = ay;
            __half2 hh; hh.x = __float2half(ax); hh.y = __float2half(ay);
            *(__half2*)&eoutf[eb] = hh;
        }
    } else {
        const float4* base = (const float4*)(g_emb2 + (long)bg * 16 * DIM);
        for (int d = tid; d < DIM / 4; d += 256) {
            float4 a = make_float4(0.f, 0.f, 0.f, 0.f);
            #pragma unroll
            for (int i = 0; i < 16; i++) {
                const float w = ws[i];
                const float4 e = base[i * (DIM / 4) + d];
                a.x += w * e.x; a.y += w * e.y; a.z += w * e.z; a.w += w * e.w;
            }
            *(float4*)&eout[(long)bg * DIM + d * 4] = a;
            const long eb = (long)bg * DIM + d * 4;
            eoutf[eb + 0] = __float2half(a.x);
            eoutf[eb + 1] = __float2half(a.y);
            eoutf[eb + 2] = __float2half(a.z);
            eoutf[eb + 3] = __float2half(a.w);
        }
    }
}

// ---------------------------------------------------------------------------
__global__ __launch_bounds__(512) void final_kernel(
    const float* __restrict__ clsW, const float* __restrict__ clsb,
    const float* __restrict__ outW, const float* __restrict__ outb,
    float* __restrict__ out)
{
    __shared__ float w3[64];
    __shared__ float outer[DIM];
    __shared__ float red[512];
    const int tid = threadIdx.x;
    const float* s3 = s_buf(2);

    if (tid == 0) {
        float sum = 0.f;
        for (int i = 0; i < 64; i++) { float e = expf(s3[i] - 1.f); w3[i] = e; sum += e; }
        const float inv = 1.f / sum;
        for (int i = 0; i < 64; i++) w3[i] *= inv;
    }
    __syncthreads();

    for (int d = tid; d < DIM; d += 512) {
        float acc = 0.f;
        #pragma unroll 8
        for (int b2 = 0; b2 < 64; b2++) acc += w3[b2] * g_emb3[b2 * DIM + d];
        outer[d] = acc;
    }
    __syncthreads();

    float acc = 0.f;
    const float* wp = clsW + tid;
    for (int d = 0; d < DIM; d++) acc += outer[d] * wp[d * NCLS];
    red[tid] = (acc + clsb[tid]) * outW[tid];
    __syncthreads();
    for (int off = 256; off; off >>= 1) {
        if (tid < off) red[tid] += red[tid + off];
        __syncthreads();
    }
    if (tid == 0) out[0] = 1.f / (1.f + expf(-(red[0] + outb[0])));
}

// ---------------------------------------------------------------------------
extern "C" void kernel_launch(void* const* d_in, const int* in_sizes, int n_in,
                              void* d_out, int out_size)
{
    const float* x    = (const float*)d_in[0];
    const float* c1w  = (const float*)d_in[1];
    const float* c1b  = (const float*)d_in[2];
    const float* c2w  = (const float*)d_in[3];
    const float* c2b  = (const float*)d_in[4];
    const float* a1W  = (const float*)d_in[5];
    const float* a1b  = (const float*)d_in[6];
    const float* a1v  = (const float*)d_in[7];
    const float* a1vb = (const float*)d_in[8];
    const float* a2W  = (const float*)d_in[9];
    const float* a2b  = (const float*)d_in[10];
    const float* a2v  = (const float*)d_in[11];
    const float* a2vb = (const float*)d_in[12];
    const float* a3W  = (const float*)d_in[13];
    const float* a3b  = (const float*)d_in[14];
    const float* a3v  = (const float*)d_in[15];
    const float* a3vb = (const float*)d_in[16];
    const float* clsW = (const float*)d_in[17];
    const float* clsb = (const float*)d_in[18];
    const float* outW = (const float*)d_in[19];
    const float* outb = (const float*)d_in[20];

    cudaFuncSetAttribute(fused_conv_kernel,
                         cudaFuncAttributeMaxDynamicSharedMemorySize, FC_SMEM);
    cudaFuncSetAttribute(att_mma_kernel,
                         cudaFuncAttributeMaxDynamicSharedMemorySize, ATT_SMEM);

    prep_all<<<3272, 256>>>(a1W, a2W, a3W, c2w);

    fused_conv_kernel<<<N_INST / 2, 256, FC_SMEM>>>(x, c1w, c1b, c2b);

    att_mma_kernel<<<N_INST / 64, 256, ATT_SMEM>>>(0, a1b, a1v, a1vb);
    segsum_kernel<<<NB1, 256>>>(0);

    att_mma_kernel<<<NB1 / 64, 256, ATT_SMEM>>>(1, a2b, a2v, a2vb);
    segsum_kernel<<<NB2, 256>>>(1);

    att_mma_kernel<<<NB2 / 64, 256, ATT_SMEM>>>(2, a3b, a3v, a3vb);
    final_kernel<<<1, 512>>>(clsW, clsb, outW, outb, (float*)d_out);
}

// round 17
// speedup vs baseline: 1.0601x; 1.0051x over previous
#include <cuda_runtime.h>
#include <cuda_fp16.h>
#include <math.h>

#define N_INST 16384
#define NB1    1024
#define NB2    64
#define DIM    1024
#define NATT   256
#define NCLS   512

// ---------------- scratch (device globals; no allocation allowed) ----------
__device__ float g_emb2[NB1 * DIM];      // fp32 bag embeddings (small)
__device__ float g_emb3[NB2 * DIM];
__device__ float g_s[N_INST + NB1 + NB2];
__device__ float g_part[3][256];         // per-CTA partial sums of exp(s-1)
// conv2 weights, transposed [n=64][k=800], fp16
__device__ __half g_w2t[64 * 800];
// embeddings as fp16 (A-side of attention GEMMs; emb1 exists ONLY as fp16)
__device__ __half g_emb1f16[N_INST * DIM];
__device__ __half g_emb2f16[NB1 * DIM];
__device__ __half g_emb3f16[NB2 * DIM];
// attention weights, transposed [n=256][k=1024], fp16, 3 levels
__device__ __half g_awt[3 * NATT * DIM];

__device__ __forceinline__ float* s_buf(int lvl) {
    return lvl == 0 ? g_s : (lvl == 1 ? g_s + N_INST : g_s + N_INST + NB1);
}

// ---------------- mma helpers ----------------------------------------------
__device__ __forceinline__ void ldsm4(unsigned& r0, unsigned& r1, unsigned& r2,
                                      unsigned& r3, unsigned a) {
    asm volatile("ldmatrix.sync.aligned.m8n8.x4.shared.b16 {%0,%1,%2,%3}, [%4];"
                 : "=r"(r0), "=r"(r1), "=r"(r2), "=r"(r3) : "r"(a));
}
__device__ __forceinline__ void mma_f16(float* c, unsigned a0, unsigned a1,
                                        unsigned a2, unsigned a3,
                                        unsigned b0, unsigned b1) {
    asm volatile(
        "mma.sync.aligned.m16n8k16.row.col.f32.f16.f16.f32 "
        "{%0,%1,%2,%3},{%4,%5,%6,%7},{%8,%9},{%0,%1,%2,%3};"
        : "+f"(c[0]), "+f"(c[1]), "+f"(c[2]), "+f"(c[3])
        : "r"(a0), "r"(a1), "r"(a2), "r"(a3), "r"(b0), "r"(b1));
}

// ---------------------------------------------------------------------------
// Prep: all weight transposes to fp16 in ONE launch.
// ---------------------------------------------------------------------------
__global__ __launch_bounds__(256) void prep_all(
    const float* __restrict__ W0, const float* __restrict__ W1,
    const float* __restrict__ W2, const float* __restrict__ w2)
{
    const int gidx = blockIdx.x * 256 + threadIdx.x;
    if (gidx < 786432) {
        const int set = gidx >> 18;
        const int idx = gidx & 262143;
        const float* W = set == 0 ? W0 : (set == 1 ? W1 : W2);
        const int n = idx >> 10, k = idx & 1023;
        g_awt[set * (NATT * DIM) + idx] = __float2half(W[k * NATT + n]);
    } else {
        const int idx = gidx - 786432;
        if (idx < 64 * 800) {
            const int n = idx / 800, k = idx - n * 800;
            g_w2t[idx] = __float2half(w2[k * 64 + n]);
        }
    }
}

// ---------------------------------------------------------------------------
// Fused conv kernel: one CTA = 2 images; 2 CTAs/SM.
// Phase A: conv1 on tensor cores (chunked row-copy im2col).
// Phase B: conv2 implicit GEMM, fp16 mma; slabs staged in PAIRS (6 barriers).
// smem map (bytes):
//   0     p1[2 img][144*40 fp16]                          23040
//   23040 shared: PhaseA Abuf (30720) | PhaseB slabs 2x21504 (43008)
//   66048 in16[2 img][784 fp16]                            3136
//   69184 w1B [32 n][40 fp16] (taps>=25 zero)              2560
//   71744 b1_s[32 f]                                        128
// ---------------------------------------------------------------------------
#define FC_SMEM 71872

__global__ __launch_bounds__(256, 2) void fused_conv_kernel(
    const float* __restrict__ x,
    const float* __restrict__ w1, const float* __restrict__ b1,
    const float* __restrict__ b2)
{
    extern __shared__ char smem[];
    const unsigned sbase = (unsigned)__cvta_generic_to_shared(smem);
    const int tid = threadIdx.x;
    const int l = tid & 31, w = tid >> 5;
    const int lane_r = ((l >> 3) & 1) * 8 + (l & 7);
    const unsigned khalf = ((l >> 4) & 1) * 16;

    __half* p1   = (__half*)smem;              // [img][144*40]
    __half* Abuf = (__half*)(smem + 23040);    // [img][192*40]
    __half* in16 = (__half*)(smem + 66048);    // [img][784]
    __half* w1B  = (__half*)(smem + 69184);    // [32][40]
    float*  b1_s = (float*)(smem + 71744);

    // ---------------- Phase A: conv1 via tensor cores ---------------------
    {
        const float* x0 = x + (size_t)blockIdx.x * 2 * 784;
        for (int i = tid; i < 1568; i += 256) in16[i] = __float2half(x0[i]);
        for (int i = tid; i < 1280; i += 256) {          // 32 rows x 40 cols
            const int n = i / 40, c = i - n * 40;
            const float v = (c < 25) ? w1[c * 32 + n] : 0.f;
            w1B[n * 40 + c] = __float2half(v);
        }
        if (tid < 32) b1_s[tid] = b1[tid];
        {
            const uint4 z4 = make_uint4(0u, 0u, 0u, 0u);
            for (int i = tid; i < 1920; i += 256)
                *(uint4*)(smem + 23040 + i * 16) = z4;
        }
        __syncthreads();

        unsigned wb[16];
        {
            const unsigned bB = sbase + 69184 + (unsigned)l * 80;
            ldsm4(wb[0],  wb[1],  wb[2],  wb[3],  bB);
            ldsm4(wb[4],  wb[5],  wb[6],  wb[7],  bB + 16);
            ldsm4(wb[8],  wb[9],  wb[10], wb[11], bB + 32);
            ldsm4(wb[12], wb[13], wb[14], wb[15], bB + 48);
        }

        const int wimg = w >> 2;
        const int wq   = w & 3;

        for (int chunk = 0; chunk < 3; chunk++) {
            for (int slot = tid; slot < 384; slot += 256) {
                const int bimg = slot >= 192;
                const int rl   = slot - bimg * 192;
                const int p    = chunk * 48 + (rl >> 2);
                const int mem  = rl & 3;
                const int pr = p / 12, pc = p - pr * 12;
                const __half* src =
                    in16 + bimg * 784 +
                    (2 * pr + (mem >> 1)) * 28 + 2 * pc + (mem & 1);
                __half* dst = Abuf + bimg * 7680 + rl * 40;
                #pragma unroll
                for (int ky = 0; ky < 5; ky++)
                    #pragma unroll
                    for (int kx = 0; kx < 5; kx++)
                        dst[ky * 5 + kx] = src[ky * 28 + kx];
            }
            __syncthreads();

            const unsigned AbB = sbase + 23040 + (unsigned)wimg * 15360;
            #pragma unroll
            for (int ti = 0; ti < 3; ti++) {
                const int tile = wq + ti * 4;
                const unsigned ar = AbB + (unsigned)(tile * 16 + lane_r) * 80;
                unsigned a0, a1, a2, a3, a4, a5, a6, a7;
                ldsm4(a0, a1, a2, a3, ar + khalf);
                ldsm4(a4, a5, a6, a7, ar + 32 + khalf);

                float acc[4][4];
                #pragma unroll
                for (int j = 0; j < 4; j++)
                    #pragma unroll
                    for (int q = 0; q < 4; q++) acc[j][q] = 0.f;
                #pragma unroll
                for (int j = 0; j < 4; j++) {
                    mma_f16(acc[j], a0, a1, a2, a3, wb[j], wb[4 + j]);
                    mma_f16(acc[j], a4, a5, a6, a7, wb[8 + j], wb[12 + j]);
                }

                const int pbase = chunk * 48 + tile * 4;
                #pragma unroll
                for (int j = 0; j < 4; j++) {
                    float m0 = acc[j][0], m1 = acc[j][1];
                    float m2 = acc[j][2], m3 = acc[j][3];
                    m0 = fmaxf(m0, __shfl_xor_sync(0xffffffffu, m0, 4));
                    m0 = fmaxf(m0, __shfl_xor_sync(0xffffffffu, m0, 8));
                    m1 = fmaxf(m1, __shfl_xor_sync(0xffffffffu, m1, 4));
                    m1 = fmaxf(m1, __shfl_xor_sync(0xffffffffu, m1, 8));
                    m2 = fmaxf(m2, __shfl_xor_sync(0xffffffffu, m2, 4));
                    m2 = fmaxf(m2, __shfl_xor_sync(0xffffffffu, m2, 8));
                    m3 = fmaxf(m3, __shfl_xor_sync(0xffffffffu, m3, 4));
                    m3 = fmaxf(m3, __shfl_xor_sync(0xffffffffu, m3, 8));
                    if ((l & 12) == 0) {
                        const int q  = l >> 4;
                        const int ch = j * 8 + 2 * (l & 3);
                        const float bA = b1_s[ch], bB2 = b1_s[ch + 1];
                        __half2 o1, o2;
                        o1.x = __float2half(fmaxf(m0 + bA, 0.f));
                        o1.y = __float2half(fmaxf(m1 + bB2, 0.f));
                        o2.x = __float2half(fmaxf(m2 + bA, 0.f));
                        o2.y = __float2half(fmaxf(m3 + bB2, 0.f));
                        __half* pp = p1 + wimg * 5760;
                        *(__half2*)&pp[(pbase + q) * 40 + ch]     = o1;
                        *(__half2*)&pp[(pbase + 2 + q) * 40 + ch] = o2;
                    }
                }
            }
            __syncthreads();
        }
    }

    // ---------------- Phase B: conv2 via fp16 tensor-core GEMM ------------
    // 8 warps = 2 img x 2 m-pairs x 2 n-halves; each warp m32 x n32.
    // Slabs staged in pairs: {0,1} -> compute ky=0,1 -> {2,3} -> ... -> {4}.
    {
        const int img = w >> 2;
        const int mp  = (w >> 1) & 1;
        const int nh  = w & 1;

        unsigned abase[2];
        #pragma unroll
        for (int s = 0; s < 2; s++) {
            const int pos = (mp * 2 + s) * 16 + lane_r;
            abase[s] = (unsigned)(((pos >> 3) * 12 + (pos & 7)) * 80);
        }

        const unsigned aHb = sbase + img * 11520;

        float acc[2][4][4];
        #pragma unroll
        for (int s = 0; s < 2; s++)
            #pragma unroll
            for (int j = 0; j < 4; j++)
                #pragma unroll
                for (int q = 0; q < 4; q++) acc[s][j][q] = 0.f;

        const char* wt = (const char*)g_w2t;

        for (int kp = 0; kp < 3; kp++) {
            const int ky0 = kp * 2;
            const int nslab = (kp == 2) ? 1 : 2;
            // stage nslab slabs (Abuf dead / previous pair consumed)
            for (int i = tid; i < 1280 * nslab; i += 256) {
                const int sl = i / 1280, ii = i - sl * 1280;
                const int n = ii / 20, c = ii - n * 20;
                *(uint4*)(smem + 23040 + sl * 21504 + n * 336 + c * 16) =
                    *(const uint4*)(wt + n * 1600 + (ky0 + sl) * 320 + c * 16);
            }
            __syncthreads();

            for (int kk = 0; kk < nslab; kk++) {
                const int ky = ky0 + kk;
                const unsigned BHb = sbase + 23040 + (unsigned)kk * 21504;
                const unsigned kyoff = (unsigned)ky * 960;
                for (int kx = 0; kx < 5; kx++) {
                    #pragma unroll
                    for (int hf = 0; hf < 2; hf++) {
                        const unsigned kb = (unsigned)(kx * 2 + hf) * 32;
                        const unsigned brow = (unsigned)(nh * 32 + l) * 336 + kb;
                        unsigned bh[8];
                        ldsm4(bh[0], bh[1], bh[2], bh[3], BHb + brow);
                        ldsm4(bh[4], bh[5], bh[6], bh[7], BHb + brow + 16);

                        #pragma unroll
                        for (int s = 0; s < 2; s++) {
                            const unsigned ab =
                                abase[s] + kyoff + kx * 80 + khalf + hf * 32;
                            unsigned ah0, ah1, ah2, ah3;
                            ldsm4(ah0, ah1, ah2, ah3, aHb + ab);
                            #pragma unroll
                            for (int j = 0; j < 4; j++)
                                mma_f16(acc[s][j], ah0, ah1, ah2, ah3,
                                        bh[j], bh[4 + j]);
                        }
                    }
                }
            }
            __syncthreads();
        }

        // epilogue: 2x2 maxpool + bias + relu -> emb1 (fp16 ONLY)
        const long row_img = (long)blockIdx.x * 2 + img;
        #pragma unroll
        for (int s = 0; s < 2; s++) {
            const int mt = mp * 2 + s;
            #pragma unroll
            for (int j = 0; j < 4; j++) {
                float v0 = fmaxf(acc[s][j][0], acc[s][j][2]);
                float v1 = fmaxf(acc[s][j][1], acc[s][j][3]);
                const float u0 = fmaxf(v0, __shfl_down_sync(0xffffffffu, v0, 4));
                const float u1 = fmaxf(v1, __shfl_down_sync(0xffffffffu, v1, 4));
                if (((l >> 2) & 1) == 0) {
                    const int pc = l >> 3;
                    const int p  = mt * 4 + pc;
                    const int nn = nh * 32 + j * 8 + 2 * (l & 3);
                    __half2 hh;
                    hh.x = __float2half(fmaxf(u0 + b2[nn], 0.f));
                    hh.y = __float2half(fmaxf(u1 + b2[nn + 1], 0.f));
                    *(__half2*)&g_emb1f16[row_img * DIM + p * 64 + nn] = hh;
                }
            }
        }
    }
}

// ---------------------------------------------------------------------------
// Attention score computation (device body), k-chunks of 128 (8 stages).
// smem: A@0 (64 rows x 272B = 17408), B@17408 (256 n x 272B = 69632),
//       sb@87040, sv@88064, wred@89088 -> 90112
// Writes per-row sigmoid scores into scores64[] (smem) for rows row0..row0+63.
// ---------------------------------------------------------------------------
#define ATT_SMEM 90112

__device__ __forceinline__ void att_scores_body(
    char* sm, unsigned sb32, int tid, int row0,
    const __half* __restrict__ ef, const __half* __restrict__ wh,
    const float* __restrict__ b, const float* __restrict__ v,
    const float* __restrict__ vb, float* scores64)
{
    float* sbf  = (float*)(sm + 87040);
    float* svf  = (float*)(sm + 88064);
    float* wred = (float*)(sm + 89088);   // [64 rows][4 quarters]
    sbf[tid] = b[tid];
    svf[tid] = v[tid];

    const int l  = tid & 31, w = tid >> 5;
    const int mp = w >> 2;
    const int nq = w & 3;
    const int lane_r = ((l >> 3) & 1) * 8 + (l & 7);
    const unsigned khalf = ((l >> 4) & 1) * 16;

    float acc[2][8][4];
    #pragma unroll
    for (int s = 0; s < 2; s++)
        #pragma unroll
        for (int j = 0; j < 8; j++)
            #pragma unroll
            for (int q = 0; q < 4; q++) acc[s][j][q] = 0.f;

    for (int kc = 0; kc < 8; kc++) {
        __syncthreads();
        const int k0 = kc * 128;
        for (int i = tid; i < 1024; i += 256) {          // A: 64 rows x 128 k
            const int r = i >> 4, c = i & 15;
            const __half* src = ef + (size_t)(row0 + r) * DIM + k0 + c * 8;
            *(uint4*)(sm + r * 272 + c * 16) = *(const uint4*)src;
        }
        for (int i = tid; i < 4096; i += 256) {          // B: 256 n x 128 k
            const int n = i >> 4, c = i & 15;
            const __half* src = wh + (size_t)n * DIM + k0 + c * 8;
            *(uint4*)(sm + 17408 + n * 272 + c * 16) = *(const uint4*)src;
        }
        __syncthreads();

        #pragma unroll
        for (int ks = 0; ks < 8; ks++) {
            unsigned ah[2][4];
            #pragma unroll
            for (int s = 0; s < 2; s++) {
                const unsigned aoff =
                    (unsigned)(mp * 32 + s * 16 + lane_r) * 272 + ks * 32 + khalf;
                ldsm4(ah[s][0], ah[s][1], ah[s][2], ah[s][3], sb32 + aoff);
            }
            #pragma unroll
            for (int g = 0; g < 2; g++) {
                const unsigned boff =
                    (unsigned)(nq * 64 + g * 32 + l) * 272 + ks * 32;
                unsigned b0h[4], b1h[4];
                ldsm4(b0h[0], b0h[1], b0h[2], b0h[3], sb32 + 17408 + boff);
                ldsm4(b1h[0], b1h[1], b1h[2], b1h[3], sb32 + 17408 + boff + 16);
                #pragma unroll
                for (int s = 0; s < 2; s++) {
                    #pragma unroll
                    for (int jj = 0; jj < 4; jj++)
                        mma_f16(acc[s][g * 4 + jj],
                                ah[s][0], ah[s][1], ah[s][2], ah[s][3],
                                b0h[jj], b1h[jj]);
                }
            }
        }
    }

    #pragma unroll
    for (int s = 0; s < 2; s++) {
        float pvA = 0.f, pvB = 0.f;
        #pragma unroll
        for (int j = 0; j < 8; j++) {
            const int n = nq * 64 + j * 8 + (l & 3) * 2;
            const float b0v = sbf[n], b1v = sbf[n + 1];
            const float v0 = svf[n], v1 = svf[n + 1];
            pvA += tanhf(acc[s][j][0] + b0v) * v0 + tanhf(acc[s][j][1] + b1v) * v1;
            pvB += tanhf(acc[s][j][2] + b0v) * v0 + tanhf(acc[s][j][3] + b1v) * v1;
        }
        pvA += __shfl_xor_sync(0xffffffffu, pvA, 1);
        pvA += __shfl_xor_sync(0xffffffffu, pvA, 2);
        pvB += __shfl_xor_sync(0xffffffffu, pvB, 1);
        pvB += __shfl_xor_sync(0xffffffffu, pvB, 2);
        if ((l & 3) == 0) {
            const int r = mp * 32 + s * 16 + (l >> 2);
            wred[r * 4 + nq]       = pvA;
            wred[(r + 8) * 4 + nq] = pvB;
        }
    }
    __syncthreads();
    if (tid < 64) {
        const float z = wred[tid * 4] + wred[tid * 4 + 1] +
                        wred[tid * 4 + 2] + wred[tid * 4 + 3] + vb[0];
        scores64[tid] = 1.f / (1.f + expf(-z));
    }
    __syncthreads();
}

// ---------------------------------------------------------------------------
// att_mma for levels 0/1: scores -> global + per-CTA partial Σexp(s-1)
// ---------------------------------------------------------------------------
__global__ __launch_bounds__(256, 2) void att_mma_kernel(
    int lvl, const float* __restrict__ b, const float* __restrict__ v,
    const float* __restrict__ vb)
{
    extern __shared__ char sm[];
    const unsigned sb32 = (unsigned)__cvta_generic_to_shared(sm);
    const int tid = threadIdx.x;
    const int row0 = blockIdx.x * 64;
    const __half* ef = lvl == 0 ? g_emb1f16 : g_emb2f16;
    const __half* wh = g_awt + (size_t)lvl * (NATT * DIM);

    __shared__ float scores[64];
    att_scores_body(sm, sb32, tid, row0, ef, wh, b, v, vb, scores);

    float* s_out = s_buf(lvl);
    if (tid < 64) {
        s_out[row0 + tid] = scores[tid];
        scores[tid] = expf(scores[tid] - 1.f);
    }
    __syncthreads();
    if (tid < 32) {
        float t = scores[tid] + scores[tid + 32];
        #pragma unroll
        for (int off = 16; off; off >>= 1)
            t += __shfl_xor_sync(0xffffffffu, t, off);
        if (tid == 0) g_part[lvl][blockIdx.x] = t;
    }
}

// ---------------------------------------------------------------------------
// Fused lvl-2 attention + outer pooling + classifier (grid = 1 CTA)
// ---------------------------------------------------------------------------
__global__ __launch_bounds__(256) void att2_final_kernel(
    const float* __restrict__ b, const float* __restrict__ v,
    const float* __restrict__ vb,
    const float* __restrict__ clsW, const float* __restrict__ clsb,
    const float* __restrict__ outW, const float* __restrict__ outb,
    float* __restrict__ out)
{
    extern __shared__ char sm[];
    const unsigned sb32 = (unsigned)__cvta_generic_to_shared(sm);
    const int tid = threadIdx.x;

    __shared__ float scores[64];
    __shared__ float w3[64];
    att_scores_body(sm, sb32, tid, 0, g_emb3f16, g_awt + 2 * (NATT * DIM),
                    b, v, vb, scores);

    // softmax over 64 scores (shift = 1.0, exact)
    if (tid == 0) {
        float sum = 0.f;
        for (int i = 0; i < 64; i++) { float e = expf(scores[i] - 1.f); w3[i] = e; sum += e; }
        const float inv = 1.f / sum;
        for (int i = 0; i < 64; i++) w3[i] *= inv;
    }
    __syncthreads();

    // outer = w3 @ emb3  (reuse A staging region for outer/red)
    float* outer = (float*)sm;            // 1024 f
    float* red   = (float*)(sm + 4096);   // 512 f
    for (int d = tid; d < DIM; d += 256) {
        float acc = 0.f;
        #pragma unroll 8
        for (int b2 = 0; b2 < 64; b2++) acc += w3[b2] * g_emb3[b2 * DIM + d];
        outer[d] = acc;
    }
    __syncthreads();

    // classifier: 512 units over 256 threads (2 units each)
    #pragma unroll
    for (int uu = 0; uu < 2; uu++) {
        const int u = tid + uu * 256;
        float acc = 0.f;
        const float* wp = clsW + u;
        for (int d = 0; d < DIM; d++) acc += outer[d] * wp[d * NCLS];
        red[u] = (acc + clsb[u]) * outW[u];
    }
    __syncthreads();
    for (int off = 256; off; off >>= 1) {
        if (tid < off && tid + off < 512) red[tid] += red[tid + off];
        __syncthreads();
    }
    if (tid == 0) out[0] = 1.f / (1.f + expf(-(red[0] + outb[0])));
}

// ---------------------------------------------------------------------------
// segsum: softmax weights from partial sums (shift=1.0) + weighted bag pooling
// ---------------------------------------------------------------------------
__global__ __launch_bounds__(256) void segsum_kernel(int lvl)
{
    __shared__ float ws[16];
    __shared__ float sred[8];
    __shared__ float ssum;
    const float* s = s_buf(lvl);
    const int bg = blockIdx.x, tid = threadIdx.x;
    const int lane = tid & 31, wrp = tid >> 5;
    const int nparts = (lvl == 0) ? 256 : 16;

    float ps = 0.f;
    for (int i = tid; i < nparts; i += 256) ps += g_part[lvl][i];
    #pragma unroll
    for (int off = 16; off; off >>= 1)
        ps += __shfl_xor_sync(0xffffffffu, ps, off);
    if (lane == 0) sred[wrp] = ps;
    __syncthreads();
    if (tid == 0) {
        float t = 0.f;
        #pragma unroll
        for (int i = 0; i < 8; i++) t += sred[i];
        ssum = t;
    }
    __syncthreads();
    if (tid < 16) ws[tid] = expf(s[bg * 16 + tid] - 1.f) / ssum;
    __syncthreads();

    float*  eout  = (lvl == 0) ? g_emb2 : g_emb3;
    __half* eoutf = (lvl == 0) ? g_emb2f16 : g_emb3f16;

    if (lvl == 0) {
        const __half2* base = (const __half2*)(g_emb1f16 + (long)bg * 16 * DIM);
        for (int d = tid; d < DIM / 2; d += 256) {
            float ax = 0.f, ay = 0.f;
            #pragma unroll
            for (int i = 0; i < 16; i++) {
                const float2 e = __half22float2(base[i * (DIM / 2) + d]);
                ax += ws[i] * e.x; ay += ws[i] * e.y;
            }
            const long eb = (long)bg * DIM + d * 2;
            eout[eb] = ax; eout[eb + 1] = ay;
            __half2 hh; hh.x = __float2half(ax); hh.y = __float2half(ay);
            *(__half2*)&eoutf[eb] = hh;
        }
    } else {
        const float4* base = (const float4*)(g_emb2 + (long)bg * 16 * DIM);
        for (int d = tid; d < DIM / 4; d += 256) {
            float4 a = make_float4(0.f, 0.f, 0.f, 0.f);
            #pragma unroll
            for (int i = 0; i < 16; i++) {
                const float w = ws[i];
                const float4 e = base[i * (DIM / 4) + d];
                a.x += w * e.x; a.y += w * e.y; a.z += w * e.z; a.w += w * e.w;
            }
            *(float4*)&eout[(long)bg * DIM + d * 4] = a;
            const long eb = (long)bg * DIM + d * 4;
            eoutf[eb + 0] = __float2half(a.x);
            eoutf[eb + 1] = __float2half(a.y);
            eoutf[eb + 2] = __float2half(a.z);
            eoutf[eb + 3] = __float2half(a.w);
        }
    }
}

// ---------------------------------------------------------------------------
extern "C" void kernel_launch(void* const* d_in, const int* in_sizes, int n_in,
                              void* d_out, int out_size)
{
    const float* x    = (const float*)d_in[0];
    const float* c1w  = (const float*)d_in[1];
    const float* c1b  = (const float*)d_in[2];
    const float* c2w  = (const float*)d_in[3];
    const float* c2b  = (const float*)d_in[4];
    const float* a1W  = (const float*)d_in[5];
    const float* a1b  = (const float*)d_in[6];
    const float* a1v  = (const float*)d_in[7];
    const float* a1vb = (const float*)d_in[8];
    const float* a2W  = (const float*)d_in[9];
    const float* a2b  = (const float*)d_in[10];
    const float* a2v  = (const float*)d_in[11];
    const float* a2vb = (const float*)d_in[12];
    const float* a3W  = (const float*)d_in[13];
    const float* a3b  = (const float*)d_in[14];
    const float* a3v  = (const float*)d_in[15];
    const float* a3vb = (const float*)d_in[16];
    const float* clsW = (const float*)d_in[17];
    const float* clsb = (const float*)d_in[18];
    const float* outW = (const float*)d_in[19];
    const float* outb = (const float*)d_in[20];

    cudaFuncSetAttribute(fused_conv_kernel,
                         cudaFuncAttributeMaxDynamicSharedMemorySize, FC_SMEM);
    cudaFuncSetAttribute(att_mma_kernel,
                         cudaFuncAttributeMaxDynamicSharedMemorySize, ATT_SMEM);
    cudaFuncSetAttribute(att2_final_kernel,
                         cudaFuncAttributeMaxDynamicSharedMemorySize, ATT_SMEM);

    prep_all<<<3272, 256>>>(a1W, a2W, a3W, c2w);

    fused_conv_kernel<<<N_INST / 2, 256, FC_SMEM>>>(x, c1w, c1b, c2b);

    att_mma_kernel<<<N_INST / 64, 256, ATT_SMEM>>>(0, a1b, a1v, a1vb);
    segsum_kernel<<<NB1, 256>>>(0);

    att_mma_kernel<<<NB1 / 64, 256, ATT_SMEM>>>(1, a2b, a2v, a2vb);
    segsum_kernel<<<NB2, 256>>>(1);

    att2_final_kernel<<<1, 256, ATT_SMEM>>>(a3b, a3v, a3vb, clsW, clsb,
                                            outW, outb, (float*)d_out);
}